// round 7
// baseline (speedup 1.0000x reference)
#include <cuda_runtime.h>
#include <math.h>
#include <stdint.h>

// ---------------- problem constants ----------------
#define NTOK 8192
#define DIM  1024
#define HID  2048
#define OUTD 1024
#define NEXP 8
#define TOPK 2

// ---------------- tiling ----------------
#define BM 256
#define BN 256

// tcgen05 engine: K=32 floats per stage (128B rows), 3-stage ring, dual 128-row D tiles
#define BKF 32
#define NSTAGE 3
#define A_STAGE_BYTES (BM * 128)     // 32 KB
#define B_STAGE_BYTES (BN * 128)     // 32 KB
#define STAGE_BYTES (A_STAGE_BYTES + B_STAGE_BYTES)   // 64 KB
#define A_HALF_BYTES (128 * 128)     // 16 KB (second M-half descriptor offset)
#define IDESC_TF32 ((1u << 4) | (2u << 7) | (2u << 10) | ((BN / 8) << 17) | ((128 / 16) << 24))

// mma.sync fallback engine (compile-correct only; not used on GB300 bench)
#define FB_BK 16
#define FB_STAGES 3
#define SP 20
#define FB_SMEM_BYTES (FB_STAGES * (128 + BN) * SP * 4)

#define TC_SMEM (NSTAGE * STAGE_BYTES + 1024)
#define DYN_SMEM (TC_SMEM > FB_SMEM_BYTES ? TC_SMEM : FB_SMEM_BYTES)

#if defined(__CUDA_ARCH_FEAT_SM103_ALL) || defined(__CUDA_ARCH_FEAT_SM100_ALL) || \
    defined(__CUDA_ARCH_FEAT_SM101_ALL) || defined(__CUDA_ARCH_FEAT_SM110_ALL)
#define TC5 1
#else
#define TC5 0
#endif

// ---------------- device scratch ----------------
__device__ float g_h1[(size_t)TOPK * NTOK * HID];
__device__ float g_h2[(size_t)TOPK * NTOK * HID];
__device__ float g_eo[(size_t)TOPK * NTOK * OUTD];
__device__ float g_s1[(size_t)NTOK * HID];
__device__ float g_s2[(size_t)NTOK * HID];
__device__ int   g_cnt[NEXP];
__device__ int   g_offs[NEXP + 1];
__device__ int   g_tmp[NEXP * NTOK];
__device__ int   g_perm[TOPK * NTOK];
__device__ int   g_eid[TOPK * NTOK];
__device__ int   g_pos[TOPK * NTOK];
__device__ float g_w[TOPK * NTOK];

__device__ __forceinline__ float* buf_ptr(int sel, const float* x, float* out) {
    switch (sel) {
        case 0: return (float*)x;
        case 1: return g_h1;
        case 2: return g_h2;
        case 3: return g_s1;
        case 4: return g_s2;
        case 5: return g_eo;
        default: return out;
    }
}

// ---------------- common helpers ----------------
__device__ __forceinline__ uint32_t smem_u32(const void* p) {
    return (uint32_t)__cvta_generic_to_shared(p);
}
__device__ __forceinline__ void cp16(uint32_t dst, const void* src) {
    asm volatile("cp.async.cg.shared.global [%0], [%1], 16;\n" :: "r"(dst), "l"(src));
}
__device__ __forceinline__ void cp_commit() {
    asm volatile("cp.async.commit_group;\n" ::);
}
__device__ __forceinline__ void cp_wait1() {
    asm volatile("cp.async.wait_group 1;\n" ::);
}
__device__ __forceinline__ void cp_wait2() {
    asm volatile("cp.async.wait_group 2;\n" ::);
}
__device__ __forceinline__ void mma_tf32(float* c, const uint32_t* a, const uint32_t* b) {
    asm volatile(
        "mma.sync.aligned.m16n8k8.row.col.f32.tf32.tf32.f32 "
        "{%0,%1,%2,%3}, {%4,%5,%6,%7}, {%8,%9}, {%0,%1,%2,%3};\n"
        : "+f"(c[0]), "+f"(c[1]), "+f"(c[2]), "+f"(c[3])
        : "r"(a[0]), "r"(a[1]), "r"(a[2]), "r"(a[3]), "r"(b[0]), "r"(b[1]));
}

#if TC5
__device__ __forceinline__ void mbar_init(uint32_t addr, uint32_t cnt) {
    asm volatile("mbarrier.init.shared.b64 [%0], %1;" :: "r"(addr), "r"(cnt) : "memory");
}
__device__ __forceinline__ void mbar_wait(uint32_t addr, uint32_t parity) {
    asm volatile(
        "{\n\t"
        ".reg .pred P1;\n\t"
        "WAIT_LOOP_%=:\n\t"
        "mbarrier.try_wait.parity.acquire.cta.shared::cta.b64 P1, [%0], %1, 0x989680;\n\t"
        "@P1 bra.uni WAIT_DONE_%=;\n\t"
        "bra.uni WAIT_LOOP_%=;\n\t"
        "WAIT_DONE_%=:\n\t"
        "}"
        :: "r"(addr), "r"(parity) : "memory");
}
// SW128 K-major descriptor: layout=2, version=1, SBO=64, LBO=1
__device__ __forceinline__ uint64_t make_desc(uint32_t addr) {
    return (uint64_t(2) << 61) | (uint64_t(1) << 46) | (uint64_t(64) << 32)
         | (uint64_t(1) << 16) | ((uint64_t)(addr >> 4) & 0x3FFF);
}
__device__ __forceinline__ void mma5_tf32_ss(uint32_t d_tmem, uint64_t a_desc, uint64_t b_desc,
                                             uint32_t idesc, bool acc) {
    uint32_t en = acc ? 1u : 0u;
    asm volatile(
        "{\n\t"
        ".reg .pred p;\n\t"
        "setp.ne.u32 p, %5, 0;\n\t"
        "tcgen05.mma.cta_group::1.kind::tf32 [%0], %1, %2, %3, {%4, %4, %4, %4}, p;\n\t"
        "}"
        :: "r"(d_tmem), "l"(a_desc), "l"(b_desc), "r"(idesc), "r"(0u), "r"(en)
        : "memory");
}
__device__ __forceinline__ void ldtm32(uint32_t* r, uint32_t tmem_addr) {
    asm volatile(
        "tcgen05.ld.sync.aligned.32x32b.x32.b32 "
        "{%0, %1, %2, %3, %4, %5, %6, %7, "
        " %8, %9, %10, %11, %12, %13, %14, %15, "
        " %16, %17, %18, %19, %20, %21, %22, %23, "
        " %24, %25, %26, %27, %28, %29, %30, %31}, [%32];"
        : "=r"(r[0]),  "=r"(r[1]),  "=r"(r[2]),  "=r"(r[3]),
          "=r"(r[4]),  "=r"(r[5]),  "=r"(r[6]),  "=r"(r[7]),
          "=r"(r[8]),  "=r"(r[9]),  "=r"(r[10]), "=r"(r[11]),
          "=r"(r[12]), "=r"(r[13]), "=r"(r[14]), "=r"(r[15]),
          "=r"(r[16]), "=r"(r[17]), "=r"(r[18]), "=r"(r[19]),
          "=r"(r[20]), "=r"(r[21]), "=r"(r[22]), "=r"(r[23]),
          "=r"(r[24]), "=r"(r[25]), "=r"(r[26]), "=r"(r[27]),
          "=r"(r[28]), "=r"(r[29]), "=r"(r[30]), "=r"(r[31])
        : "r"(tmem_addr));
}
#endif  // TC5

// ---------------- reset / gate / scan / compact ----------------
__global__ void reset_kernel() {
    if (threadIdx.x < NEXP) g_cnt[threadIdx.x] = 0;
}

__global__ void gate_kernel(const float* __restrict__ x, const float* __restrict__ Wg) {
    int gwarp = (blockIdx.x * blockDim.x + threadIdx.x) >> 5;
    int lane  = threadIdx.x & 31;
    if (gwarp >= NTOK) return;
    const float* xr = x + (size_t)gwarp * DIM;

    float sc[NEXP];
#pragma unroll
    for (int e = 0; e < NEXP; ++e) {
        const float* wr = Wg + (size_t)e * DIM;
        float s = 0.f;
        for (int d = lane; d < DIM; d += 32) s += xr[d] * wr[d];
#pragma unroll
        for (int o = 16; o > 0; o >>= 1) s += __shfl_xor_sync(0xffffffffu, s, o);
        sc[e] = s;
    }
    if (lane == 0) {
        float mx = sc[0];
#pragma unroll
        for (int e = 1; e < NEXP; ++e) mx = fmaxf(mx, sc[e]);
        float ex[NEXP], sum = 0.f;
#pragma unroll
        for (int e = 0; e < NEXP; ++e) { ex[e] = expf(sc[e] - mx); sum += ex[e]; }
        float p[NEXP];
#pragma unroll
        for (int e = 0; e < NEXP; ++e) p[e] = ex[e] / sum;
        int i0 = 0;
#pragma unroll
        for (int e = 1; e < NEXP; ++e) if (p[e] > p[i0]) i0 = e;
        int i1 = -1;
#pragma unroll
        for (int e = 0; e < NEXP; ++e) {
            if (e == i0) continue;
            if (i1 < 0 || p[e] > p[i1]) i1 = e;
        }
        float p0 = p[i0], p1 = p[i1];
        float s2 = p0 + p1 + 1e-20f;
        float w0 = p0 / s2, w1 = p1 / s2;

        int pos0 = atomicAdd(&g_cnt[i0], 1);
        g_tmp[i0 * NTOK + pos0] = gwarp;
        int pos1 = atomicAdd(&g_cnt[i1], 1);
        g_tmp[i1 * NTOK + pos1] = gwarp;

        g_eid[2 * gwarp + 0] = i0; g_pos[2 * gwarp + 0] = pos0; g_w[2 * gwarp + 0] = w0;
        g_eid[2 * gwarp + 1] = i1; g_pos[2 * gwarp + 1] = pos1; g_w[2 * gwarp + 1] = w1;
    }
}

__global__ void scan_kernel() {
    if (threadIdx.x == 0) {
        int acc = 0;
        g_offs[0] = 0;
        for (int e = 0; e < NEXP; ++e) { acc += g_cnt[e]; g_offs[e + 1] = acc; }
    }
}

__global__ void compact_kernel() {
    int e = blockIdx.x;
    int base = g_offs[e];
    int c = g_cnt[e];
    for (int i = threadIdx.x; i < c; i += blockDim.x)
        g_perm[base + i] = g_tmp[e * NTOK + i];
}

// ---------------- dual-engine tf32 NT GEMM, 256x256 tile ----------------
// C[m,n] = epi( sum_k A[m,k]*B[n,k] + bias[n] ).  MODE 0: relu->BN.  MODE 1: sigmoid.
template<int MODE>
__global__ void __launch_bounds__(256, 1) __cluster_dims__(1, 1, 1)
gemm5(int aSel, int cSel, const float* __restrict__ xin, float* __restrict__ outp,
      const float* __restrict__ B,
      const float* __restrict__ bias, const float* __restrict__ gam,
      const float* __restrict__ bet, const float* __restrict__ mu,
      const float* __restrict__ var,
      int usePerm, int routed, int Mfixed, int Kd, int Ncols)
{
    extern __shared__ float dyn[];

    const float* A = buf_ptr(aSel, xin, outp);
    float*       C = buf_ptr(cSel, xin, outp);

    int e = blockIdx.z;
    int M, rowBase;
    if (routed) { M = g_cnt[e]; rowBase = g_offs[e]; }
    else        { M = Mfixed;   rowBase = 0; }

    int m0 = blockIdx.y * BM;
    if (m0 >= M) return;
    int n0 = blockIdx.x * BN;
    const float* Bp = B + (size_t)e * Ncols * Kd;

    int tid = threadIdx.x, wid = tid >> 5, lane = tid & 31;

#if TC5
    // ================= tcgen05 tf32 SS engine, dual D tiles =================
    __shared__ uint64_t s_mbar[NSTAGE];
    __shared__ uint32_t s_tmem;
    __shared__ float    s_ep[5][BN];

    uint32_t base = (smem_u32(dyn) + 1023u) & ~1023u;

    {   // epilogue params -> smem (one column per thread)
        int n = n0 + tid;
        s_ep[0][tid] = bias[(size_t)e * Ncols + n];
        if (MODE == 0) {
            s_ep[1][tid] = gam[(size_t)e * Ncols + n];
            s_ep[2][tid] = bet[(size_t)e * Ncols + n];
            s_ep[3][tid] = mu[(size_t)e * Ncols + n];
            s_ep[4][tid] = rsqrtf(var[(size_t)e * Ncols + n] + 1e-5f);
        }
    }

    if (wid == 0) {
        asm volatile("tcgen05.alloc.cta_group::1.sync.aligned.shared::cta.b32 [%0], %1;"
                     :: "r"(smem_u32(&s_tmem)), "r"(512) : "memory");
        asm volatile("tcgen05.relinquish_alloc_permit.cta_group::1.sync.aligned;");
    }
    if (tid == 0) {
        for (int s = 0; s < NSTAGE; ++s) mbar_init(smem_u32(&s_mbar[s]), 1);
    }
    __syncthreads();
    uint32_t tmem;
    asm volatile("ld.shared.b32 %0, [%1];" : "=r"(tmem) : "r"(smem_u32(&s_tmem)));

    // producer chunk mapping: 8 A-chunks + 8 B-chunks per thread (16B each, SW128 swizzle)
    const float* srcA[8]; uint32_t dstA[8];
#pragma unroll
    for (int i = 0; i < 8; ++i) {
        int idx = tid + i * 256;       // 0..2047
        int r = idx >> 3, c = idx & 7; // row 0..255, chunk 0..7
        int slot = rowBase + min(m0 + r, M - 1);
        int gr = usePerm ? g_perm[slot] : slot;
        srcA[i] = A + (size_t)gr * Kd + c * 4;
        dstA[i] = base + (uint32_t)(r * 128 + ((c ^ (r & 7)) * 16));
    }
    const float* srcB[8]; uint32_t dstB[8];
#pragma unroll
    for (int i = 0; i < 8; ++i) {
        int idx = tid + i * 256;
        int r = idx >> 3, c = idx & 7;
        srcB[i] = Bp + (size_t)(n0 + r) * Kd + c * 4;
        dstB[i] = base + A_STAGE_BYTES + (uint32_t)(r * 128 + ((c ^ (r & 7)) * 16));
    }

    int nk = Kd / BKF;

    // prologue: stages 0, 1
#pragma unroll
    for (int s = 0; s < 2; ++s) {
        uint32_t so = s * STAGE_BYTES;
        size_t  ko = (size_t)s * BKF;
#pragma unroll
        for (int i = 0; i < 8; ++i) cp16(dstA[i] + so, srcA[i] + ko);
#pragma unroll
        for (int i = 0; i < 8; ++i) cp16(dstB[i] + so, srcB[i] + ko);
        cp_commit();
    }

    for (int kt = 0; kt < nk; ++kt) {
        int st = kt + 2;
        if (st < nk) {
            if (kt >= 1) {                 // stage kt+2 reuses buffer of stage kt-1
                int w = kt - 1;
                mbar_wait(smem_u32(&s_mbar[w % NSTAGE]), (w / NSTAGE) & 1);
            }
            uint32_t so = (uint32_t)(st % NSTAGE) * STAGE_BYTES;
            size_t  ko = (size_t)st * BKF;
#pragma unroll
            for (int i = 0; i < 8; ++i) cp16(dstA[i] + so, srcA[i] + ko);
#pragma unroll
            for (int i = 0; i < 8; ++i) cp16(dstB[i] + so, srcB[i] + ko);
        }
        cp_commit();
        cp_wait2();
        __syncthreads();

        if (tid == 0) {
            asm volatile("fence.proxy.async.shared::cta;" ::: "memory");
            uint32_t so = (uint32_t)(kt % NSTAGE) * STAGE_BYTES;
            uint64_t ad0 = make_desc(base + so);
            uint64_t ad1 = make_desc(base + so + A_HALF_BYTES);
            uint64_t bd  = make_desc(base + so + A_STAGE_BYTES);
            bool accb = (kt > 0);
#pragma unroll
            for (int ks = 0; ks < 4; ++ks) {
                bool acc = accb || (ks > 0);
                mma5_tf32_ss(tmem,       ad0 + ks * 2, bd + ks * 2, IDESC_TF32, acc);
                mma5_tf32_ss(tmem + 256, ad1 + ks * 2, bd + ks * 2, IDESC_TF32, acc);
            }
            asm volatile(
                "tcgen05.commit.cta_group::1.mbarrier::arrive::one.shared::cluster.b64 [%0];"
                :: "r"(smem_u32(&s_mbar[kt % NSTAGE])) : "memory");
        }
    }

    {
        int w = nk - 1;
        mbar_wait(smem_u32(&s_mbar[w % NSTAGE]), (w / NSTAGE) & 1);
    }
    asm volatile("tcgen05.fence::after_thread_sync;" ::: "memory");

    // epilogue: warps 0-3 -> D0 (rows 0-127), warps 4-7 -> D1 (rows 128-255)
    {
        int half = wid >> 2;
        int sub  = wid & 3;
        int mloc = half * 128 + sub * 32 + lane;
        int mr   = m0 + mloc;
        bool valid = (mr < M);
        uint32_t tbase = tmem + half * 256;
        float* crow = C + (size_t)(rowBase + mr) * Ncols + n0;
#pragma unroll
        for (int cc = 0; cc < 8; ++cc) {
            uint32_t r[32];
            ldtm32(r, tbase + cc * 32);
            asm volatile("tcgen05.wait::ld.sync.aligned;" ::: "memory");
            if (valid) {
#pragma unroll
                for (int j = 0; j < 32; j += 4) {
                    float o[4];
#pragma unroll
                    for (int q = 0; q < 4; ++q) {
                        int n = cc * 32 + j + q;
                        float v = __uint_as_float(r[j + q]) + s_ep[0][n];
                        if (MODE == 0) {
                            v = fmaxf(v, 0.f);
                            v = s_ep[1][n] * (v - s_ep[3][n]) * s_ep[4][n] + s_ep[2][n];
                        } else {
                            v = 1.f / (1.f + expf(-v));
                        }
                        o[q] = v;
                    }
                    *(float4*)(crow + cc * 32 + j) = make_float4(o[0], o[1], o[2], o[3]);
                }
            }
        }
    }

    __syncthreads();
    if (wid == 0) {
        asm volatile("tcgen05.dealloc.cta_group::1.sync.aligned.b32 %0, %1;"
                     :: "r"(tmem), "r"(512));
    }

#else
    // ============ mma.sync tf32 fallback (compile-correct; two 128-row halves) ============
    float* AsBase = dyn;
    float* BsBase = dyn + FB_STAGES * 128 * SP;

    int warp = wid;
    int wm   = warp & 1;
    int wn   = warp >> 1;
    int g    = lane >> 2;
    int t    = lane & 3;

    for (int halfTile = 0; halfTile < 2; ++halfTile) {
        int m0h = m0 + halfTile * 128;
        if (m0h >= M) break;

        int rA[2], kA[2];
        const float* srcA[2];
        uint32_t dA[2];
        uint32_t sA = smem_u32(AsBase);
        uint32_t sB = smem_u32(BsBase);
#pragma unroll
        for (int i = 0; i < 2; ++i) {
            int c = tid + i * 256;
            rA[i] = c >> 2; kA[i] = (c & 3) * 4;
            int slot = rowBase + min(m0h + rA[i], M - 1);
            int gr = usePerm ? g_perm[slot] : slot;
            srcA[i] = A + (size_t)gr * Kd + kA[i];
            dA[i] = sA + (uint32_t)(rA[i] * SP + kA[i]) * 4;
        }
        const float* srcB[4];
        uint32_t dB[4];
#pragma unroll
        for (int i = 0; i < 4; ++i) {
            int c = tid + i * 256;
            int rB = c >> 2, kB = (c & 3) * 4;
            srcB[i] = Bp + (size_t)(n0 + rB) * Kd + kB;
            dB[i] = sB + (uint32_t)(rB * SP + kB) * 4;
        }
        const uint32_t stA = 128 * SP * 4;
        const uint32_t stB = BN * SP * 4;

        float acc[4][8][4];
#pragma unroll
        for (int i = 0; i < 4; ++i)
#pragma unroll
            for (int j = 0; j < 8; ++j)
#pragma unroll
                for (int q = 0; q < 4; ++q) acc[i][j][q] = 0.f;

        int nk = Kd >> 4;

#pragma unroll
        for (int s = 0; s < 2; ++s) {
            size_t ko = (size_t)s * FB_BK;
#pragma unroll
            for (int i = 0; i < 2; ++i) cp16(dA[i] + s * stA, srcA[i] + ko);
#pragma unroll
            for (int i = 0; i < 4; ++i) cp16(dB[i] + s * stB, srcB[i] + ko);
            cp_commit();
        }

        for (int kt = 0; kt < nk; ++kt) {
            cp_wait1();
            __syncthreads();

            if (kt + 2 < nk) {
                int s = (kt + 2) % FB_STAGES;
                size_t ko = (size_t)(kt + 2) * FB_BK;
#pragma unroll
                for (int i = 0; i < 2; ++i) cp16(dA[i] + s * stA, srcA[i] + ko);
#pragma unroll
                for (int i = 0; i < 4; ++i) cp16(dB[i] + s * stB, srcB[i] + ko);
            }
            cp_commit();

            int cur = kt % FB_STAGES;
            const float* As = AsBase + cur * 128 * SP;
            const float* Bs = BsBase + cur * BN * SP;

#pragma unroll
            for (int kk = 0; kk < FB_BK; kk += 8) {
                uint32_t a[4][4], b[8][2];
#pragma unroll
                for (int mi = 0; mi < 4; ++mi) {
                    int r = wm * 64 + mi * 16 + g;
                    a[mi][0] = __float_as_uint(As[(r    ) * SP + kk + t]);
                    a[mi][1] = __float_as_uint(As[(r + 8) * SP + kk + t]);
                    a[mi][2] = __float_as_uint(As[(r    ) * SP + kk + t + 4]);
                    a[mi][3] = __float_as_uint(As[(r + 8) * SP + kk + t + 4]);
                }
#pragma unroll
                for (int ni = 0; ni < 8; ++ni) {
                    int r = wn * 64 + ni * 8 + g;
                    b[ni][0] = __float_as_uint(Bs[r * SP + kk + t]);
                    b[ni][1] = __float_as_uint(Bs[r * SP + kk + t + 4]);
                }
#pragma unroll
                for (int mi = 0; mi < 4; ++mi)
#pragma unroll
                    for (int ni = 0; ni < 8; ++ni)
                        mma_tf32(acc[mi][ni], a[mi], b[ni]);
            }
        }

        const float* biasp = bias + (size_t)e * Ncols;
        const float* gp = (MODE == 0) ? gam + (size_t)e * Ncols : nullptr;
        const float* bp = (MODE == 0) ? bet + (size_t)e * Ncols : nullptr;
        const float* mp = (MODE == 0) ? mu  + (size_t)e * Ncols : nullptr;
        const float* vp = (MODE == 0) ? var + (size_t)e * Ncols : nullptr;

#pragma unroll
        for (int ni = 0; ni < 8; ++ni) {
            int cb = n0 + wn * 64 + ni * 8 + 2 * t;
            float bb0 = biasp[cb], bb1 = biasp[cb + 1];
            float gg0 = 0, gg1 = 0, be0 = 0, be1 = 0, mm0 = 0, mm1 = 0, iv0 = 0, iv1 = 0;
            if (MODE == 0) {
                gg0 = gp[cb]; gg1 = gp[cb + 1];
                be0 = bp[cb]; be1 = bp[cb + 1];
                mm0 = mp[cb]; mm1 = mp[cb + 1];
                iv0 = rsqrtf(vp[cb] + 1e-5f);
                iv1 = rsqrtf(vp[cb + 1] + 1e-5f);
            }
#pragma unroll
            for (int mi = 0; mi < 4; ++mi) {
#pragma unroll
                for (int half = 0; half < 2; ++half) {
                    int mr = m0h + wm * 64 + mi * 16 + g + half * 8;
                    if (mr < M) {
                        float v0 = acc[mi][ni][half * 2 + 0] + bb0;
                        float v1 = acc[mi][ni][half * 2 + 1] + bb1;
                        if (MODE == 0) {
                            v0 = fmaxf(v0, 0.f);
                            v1 = fmaxf(v1, 0.f);
                            v0 = gg0 * (v0 - mm0) * iv0 + be0;
                            v1 = gg1 * (v1 - mm1) * iv1 + be1;
                        } else {
                            v0 = 1.f / (1.f + expf(-v0));
                            v1 = 1.f / (1.f + expf(-v1));
                        }
                        float* crow = C + (size_t)(rowBase + mr) * Ncols + cb;
                        *(float2*)crow = make_float2(v0, v1);
                    }
                }
            }
        }
        __syncthreads();
    }
#endif  // TC5
}

// ---------------- combine ----------------
__global__ void combine_kernel(float* __restrict__ out) {
    int n = blockIdx.x;
    int e0 = g_eid[2 * n + 0], e1 = g_eid[2 * n + 1];
    int s0 = g_offs[e0] + g_pos[2 * n + 0];
    int s1 = g_offs[e1] + g_pos[2 * n + 1];
    float w0 = g_w[2 * n + 0], w1 = g_w[2 * n + 1];
    const float* r0 = g_eo + (size_t)s0 * OUTD;
    const float* r1 = g_eo + (size_t)s1 * OUTD;
    float* orow = out + (size_t)n * OUTD;
    for (int c = threadIdx.x; c < OUTD; c += blockDim.x)
        orow[c] += w0 * r0[c] + w1 * r1[c];
}

// ---------------- launch ----------------
extern "C" void kernel_launch(void* const* d_in, const int* in_sizes, int n_in,
                              void* d_out, int out_size) {
    const float* x   = (const float*)d_in[0];
    const float* Wg  = (const float*)d_in[1];
    const float* W1  = (const float*)d_in[2];
    const float* b1  = (const float*)d_in[3];
    const float* g1  = (const float*)d_in[4];
    const float* be1 = (const float*)d_in[5];
    const float* m1  = (const float*)d_in[6];
    const float* v1  = (const float*)d_in[7];
    const float* W2  = (const float*)d_in[8];
    const float* b2  = (const float*)d_in[9];
    const float* g2  = (const float*)d_in[10];
    const float* be2 = (const float*)d_in[11];
    const float* m2  = (const float*)d_in[12];
    const float* v2  = (const float*)d_in[13];
    const float* W3  = (const float*)d_in[14];
    const float* b3  = (const float*)d_in[15];
    const float* sW1 = (const float*)d_in[16];
    const float* sb1 = (const float*)d_in[17];
    const float* sg1 = (const float*)d_in[18];
    const float* sbe1= (const float*)d_in[19];
    const float* sm1 = (const float*)d_in[20];
    const float* sv1 = (const float*)d_in[21];
    const float* sW2 = (const float*)d_in[22];
    const float* sb2 = (const float*)d_in[23];
    const float* sg2 = (const float*)d_in[24];
    const float* sbe2= (const float*)d_in[25];
    const float* sm2 = (const float*)d_in[26];
    const float* sv2 = (const float*)d_in[27];
    const float* sW3 = (const float*)d_in[28];
    const float* sb3 = (const float*)d_in[29];
    float* out = (float*)d_out;

    cudaFuncSetAttribute(gemm5<0>, cudaFuncAttributeMaxDynamicSharedMemorySize, DYN_SMEM);
    cudaFuncSetAttribute(gemm5<1>, cudaFuncAttributeMaxDynamicSharedMemorySize, DYN_SMEM);

    reset_kernel<<<1, 32>>>();
    gate_kernel<<<NTOK / 8, 256>>>(x, Wg);
    scan_kernel<<<1, 1>>>();
    compact_kernel<<<NEXP, 256>>>();

    // routed experts: x -> h1 -> h2 -> eo
    gemm5<0><<<dim3(HID / BN, NTOK / BM, NEXP), 256, DYN_SMEM>>>(
        0, 1, x, out, W1, b1, g1, be1, m1, v1, 1, 1, 0, DIM, HID);
    gemm5<0><<<dim3(HID / BN, NTOK / BM, NEXP), 256, DYN_SMEM>>>(
        1, 2, x, out, W2, b2, g2, be2, m2, v2, 0, 1, 0, HID, HID);
    gemm5<1><<<dim3(OUTD / BN, NTOK / BM, NEXP), 256, DYN_SMEM>>>(
        2, 5, x, out, W3, b3, nullptr, nullptr, nullptr, nullptr, 0, 1, 0, HID, OUTD);

    // shared expert: x -> s1 -> s2 -> out
    gemm5<0><<<dim3(HID / BN, NTOK / BM, 1), 256, DYN_SMEM>>>(
        0, 3, x, out, sW1, sb1, sg1, sbe1, sm1, sv1, 0, 0, NTOK, DIM, HID);
    gemm5<0><<<dim3(HID / BN, NTOK / BM, 1), 256, DYN_SMEM>>>(
        3, 4, x, out, sW2, sb2, sg2, sbe2, sm2, sv2, 0, 0, NTOK, HID, HID);
    gemm5<1><<<dim3(OUTD / BN, NTOK / BM, 1), 256, DYN_SMEM>>>(
        4, 6, x, out, sW3, sb3, nullptr, nullptr, nullptr, nullptr, 0, 0, NTOK, HID, OUTD);

    combine_kernel<<<NTOK, 256>>>(out);
}

// round 10
// speedup vs baseline: 1.1085x; 1.1085x over previous
#include <cuda_runtime.h>
#include <math.h>
#include <stdint.h>

// ---------------- problem constants ----------------
#define NTOK 8192
#define DIM  1024
#define HID  2048
#define OUTD 1024
#define NEXP 8
#define TOPK 2

// ---------------- tiling ----------------
#define BM 128
#define BN 256
#define BKF 32                        // K floats per stage (128 B rows)
#define NSTAGE 2
#define A_STAGE_BYTES (BM * 128)      // 16 KB
#define B_STAGE_BYTES (BN * 128)      // 32 KB
#define STAGE_BYTES (A_STAGE_BYTES + B_STAGE_BYTES)   // 48 KB
#define IDESC_TF32 ((1u << 4) | (2u << 7) | (2u << 10) | ((BN / 8) << 17) | ((BM / 16) << 24))

// mma.sync fallback engine (compile-correct; not used on GB300 bench)
#define FB_BK 16
#define FB_STAGES 3
#define SP 20
#define FB_SMEM_BYTES (FB_STAGES * (BM + BN) * SP * 4)   // 92160

#define TC_SMEM (NSTAGE * STAGE_BYTES + 1024)            // 99328
#define DYN_SMEM (TC_SMEM > FB_SMEM_BYTES ? TC_SMEM : FB_SMEM_BYTES)

#if defined(__CUDA_ARCH_FEAT_SM103_ALL) || defined(__CUDA_ARCH_FEAT_SM100_ALL) || \
    defined(__CUDA_ARCH_FEAT_SM101_ALL) || defined(__CUDA_ARCH_FEAT_SM110_ALL)
#define TC5 1
#else
#define TC5 0
#endif

// ---------------- device scratch ----------------
__device__ float g_h1[(size_t)TOPK * NTOK * HID];
__device__ float g_h2[(size_t)TOPK * NTOK * HID];
__device__ float g_eo[(size_t)TOPK * NTOK * OUTD];
__device__ float g_s1[(size_t)NTOK * HID];
__device__ float g_s2[(size_t)NTOK * HID];
__device__ int   g_cnt[NEXP];
__device__ int   g_offs[NEXP + 1];
__device__ int   g_tmp[NEXP * NTOK];
__device__ int   g_perm[TOPK * NTOK];
__device__ int   g_eid[TOPK * NTOK];
__device__ int   g_pos[TOPK * NTOK];
__device__ float g_w[TOPK * NTOK];

__device__ __forceinline__ float* buf_ptr(int sel, const float* x, float* out) {
    switch (sel) {
        case 0: return (float*)x;
        case 1: return g_h1;
        case 2: return g_h2;
        case 3: return g_s1;
        case 4: return g_s2;
        case 5: return g_eo;
        default: return out;
    }
}

// ---------------- common helpers ----------------
__device__ __forceinline__ uint32_t smem_u32(const void* p) {
    return (uint32_t)__cvta_generic_to_shared(p);
}
__device__ __forceinline__ void cp16(uint32_t dst, const void* src) {
    asm volatile("cp.async.cg.shared.global [%0], [%1], 16;\n" :: "r"(dst), "l"(src));
}
__device__ __forceinline__ void cp_commit() {
    asm volatile("cp.async.commit_group;\n" ::);
}
__device__ __forceinline__ void cp_wait1() {
    asm volatile("cp.async.wait_group 1;\n" ::);
}
__device__ __forceinline__ void mma_tf32(float* c, const uint32_t* a, const uint32_t* b) {
    asm volatile(
        "mma.sync.aligned.m16n8k8.row.col.f32.tf32.tf32.f32 "
        "{%0,%1,%2,%3}, {%4,%5,%6,%7}, {%8,%9}, {%0,%1,%2,%3};\n"
        : "+f"(c[0]), "+f"(c[1]), "+f"(c[2]), "+f"(c[3])
        : "r"(a[0]), "r"(a[1]), "r"(a[2]), "r"(a[3]), "r"(b[0]), "r"(b[1]));
}

#if TC5
__device__ __forceinline__ void mbar_init(uint32_t addr, uint32_t cnt) {
    asm volatile("mbarrier.init.shared.b64 [%0], %1;" :: "r"(addr), "r"(cnt) : "memory");
}
__device__ __forceinline__ void mbar_wait(uint32_t addr, uint32_t parity) {
    asm volatile(
        "{\n\t"
        ".reg .pred P1;\n\t"
        "WAIT_LOOP_%=:\n\t"
        "mbarrier.try_wait.parity.acquire.cta.shared::cta.b64 P1, [%0], %1, 0x989680;\n\t"
        "@P1 bra.uni WAIT_DONE_%=;\n\t"
        "bra.uni WAIT_LOOP_%=;\n\t"
        "WAIT_DONE_%=:\n\t"
        "}"
        :: "r"(addr), "r"(parity) : "memory");
}
// SW128 K-major descriptor: layout=2, version=1, SBO=64, LBO=1
__device__ __forceinline__ uint64_t make_desc(uint32_t addr) {
    return (uint64_t(2) << 61) | (uint64_t(1) << 46) | (uint64_t(64) << 32)
         | (uint64_t(1) << 16) | ((uint64_t)(addr >> 4) & 0x3FFF);
}
__device__ __forceinline__ void mma5_tf32_ss(uint32_t d_tmem, uint64_t a_desc, uint64_t b_desc,
                                             uint32_t idesc, bool acc) {
    uint32_t en = acc ? 1u : 0u;
    asm volatile(
        "{\n\t"
        ".reg .pred p;\n\t"
        "setp.ne.u32 p, %5, 0;\n\t"
        "tcgen05.mma.cta_group::1.kind::tf32 [%0], %1, %2, %3, {%4, %4, %4, %4}, p;\n\t"
        "}"
        :: "r"(d_tmem), "l"(a_desc), "l"(b_desc), "r"(idesc), "r"(0u), "r"(en)
        : "memory");
}
__device__ __forceinline__ void ldtm32(uint32_t* r, uint32_t tmem_addr) {
    asm volatile(
        "tcgen05.ld.sync.aligned.32x32b.x32.b32 "
        "{%0, %1, %2, %3, %4, %5, %6, %7, "
        " %8, %9, %10, %11, %12, %13, %14, %15, "
        " %16, %17, %18, %19, %20, %21, %22, %23, "
        " %24, %25, %26, %27, %28, %29, %30, %31}, [%32];"
        : "=r"(r[0]),  "=r"(r[1]),  "=r"(r[2]),  "=r"(r[3]),
          "=r"(r[4]),  "=r"(r[5]),  "=r"(r[6]),  "=r"(r[7]),
          "=r"(r[8]),  "=r"(r[9]),  "=r"(r[10]), "=r"(r[11]),
          "=r"(r[12]), "=r"(r[13]), "=r"(r[14]), "=r"(r[15]),
          "=r"(r[16]), "=r"(r[17]), "=r"(r[18]), "=r"(r[19]),
          "=r"(r[20]), "=r"(r[21]), "=r"(r[22]), "=r"(r[23]),
          "=r"(r[24]), "=r"(r[25]), "=r"(r[26]), "=r"(r[27]),
          "=r"(r[28]), "=r"(r[29]), "=r"(r[30]), "=r"(r[31])
        : "r"(tmem_addr));
}
#endif  // TC5

// ---------------- reset / gate / scan / compact ----------------
__global__ void reset_kernel() {
    if (threadIdx.x < NEXP) g_cnt[threadIdx.x] = 0;
}

__global__ void gate_kernel(const float* __restrict__ x, const float* __restrict__ Wg) {
    int gwarp = (blockIdx.x * blockDim.x + threadIdx.x) >> 5;
    int lane  = threadIdx.x & 31;
    if (gwarp >= NTOK) return;
    const float* xr = x + (size_t)gwarp * DIM;

    float sc[NEXP];
#pragma unroll
    for (int e = 0; e < NEXP; ++e) {
        const float* wr = Wg + (size_t)e * DIM;
        float s = 0.f;
        for (int d = lane; d < DIM; d += 32) s += xr[d] * wr[d];
#pragma unroll
        for (int o = 16; o > 0; o >>= 1) s += __shfl_xor_sync(0xffffffffu, s, o);
        sc[e] = s;
    }
    if (lane == 0) {
        float mx = sc[0];
#pragma unroll
        for (int e = 1; e < NEXP; ++e) mx = fmaxf(mx, sc[e]);
        float ex[NEXP], sum = 0.f;
#pragma unroll
        for (int e = 0; e < NEXP; ++e) { ex[e] = expf(sc[e] - mx); sum += ex[e]; }
        float p[NEXP];
#pragma unroll
        for (int e = 0; e < NEXP; ++e) p[e] = ex[e] / sum;
        int i0 = 0;
#pragma unroll
        for (int e = 1; e < NEXP; ++e) if (p[e] > p[i0]) i0 = e;
        int i1 = -1;
#pragma unroll
        for (int e = 0; e < NEXP; ++e) {
            if (e == i0) continue;
            if (i1 < 0 || p[e] > p[i1]) i1 = e;
        }
        float p0 = p[i0], p1 = p[i1];
        float s2 = p0 + p1 + 1e-20f;
        float w0 = p0 / s2, w1 = p1 / s2;

        int pos0 = atomicAdd(&g_cnt[i0], 1);
        g_tmp[i0 * NTOK + pos0] = gwarp;
        int pos1 = atomicAdd(&g_cnt[i1], 1);
        g_tmp[i1 * NTOK + pos1] = gwarp;

        g_eid[2 * gwarp + 0] = i0; g_pos[2 * gwarp + 0] = pos0; g_w[2 * gwarp + 0] = w0;
        g_eid[2 * gwarp + 1] = i1; g_pos[2 * gwarp + 1] = pos1; g_w[2 * gwarp + 1] = w1;
    }
}

__global__ void scan_kernel() {
    if (threadIdx.x == 0) {
        int acc = 0;
        g_offs[0] = 0;
        for (int e = 0; e < NEXP; ++e) { acc += g_cnt[e]; g_offs[e + 1] = acc; }
    }
}

__global__ void compact_kernel() {
    int e = blockIdx.x;
    int base = g_offs[e];
    int c = g_cnt[e];
    for (int i = threadIdx.x; i < c; i += blockDim.x)
        g_perm[base + i] = g_tmp[e * NTOK + i];
}

// ---------------- merged dual-engine tf32 NT GEMM ----------------
// blockIdx.x = ex * xTiles + xt; ex in [0, NEXP] where NEXP == shared expert.
// C[m,n] = epi( sum_k A[m,k]*B[n,k] + bias[n] ).  MODE 0: relu->BN.  MODE 1: sigmoid.
template<int MODE>
__global__ void __launch_bounds__(256, 2) __cluster_dims__(1, 1, 1)
gemm5(int aSelR, int cSelR, int aSelS, int cSelS,
      const float* __restrict__ xin, float* __restrict__ outp,
      const float* __restrict__ W,   const float* __restrict__ sW,
      const float* __restrict__ bias,const float* __restrict__ sbias,
      const float* __restrict__ gam, const float* __restrict__ sgam,
      const float* __restrict__ bet, const float* __restrict__ sbet,
      const float* __restrict__ mu,  const float* __restrict__ smu,
      const float* __restrict__ var, const float* __restrict__ svar,
      int usePerm, int Kd, int Ncols, int xTiles)
{
    extern __shared__ float dyn[];

    int ex = blockIdx.x / xTiles;
    int xt = blockIdx.x - ex * xTiles;
    bool sh = (ex == NEXP);

    int M       = sh ? NTOK : g_cnt[ex];
    int rowBase = sh ? 0    : g_offs[ex];
    int m0 = blockIdx.y * BM;
    if (m0 >= M) return;
    int n0 = xt * BN;

    const float* A = buf_ptr(sh ? aSelS : aSelR, xin, outp);
    float*       C = buf_ptr(sh ? cSelS : cSelR, xin, outp);
    const float* Bp    = sh ? sW    : W    + (size_t)ex * Ncols * Kd;
    const float* biasp = sh ? sbias : bias + (size_t)ex * Ncols;
    int up = sh ? 0 : usePerm;

    int tid = threadIdx.x, wid = tid >> 5, lane = tid & 31;

#if TC5
    // ================= tcgen05 tf32 SS engine, 2-stage ring, occupancy 2 =================
    __shared__ uint64_t s_mbar[NSTAGE];
    __shared__ uint32_t s_tmem;
    __shared__ float    s_ep[5][BN];

    uint32_t base = (smem_u32(dyn) + 1023u) & ~1023u;

    {   // epilogue params -> smem (one column per thread)
        s_ep[0][tid] = biasp[n0 + tid];
        if (MODE == 0) {
            const float* gp = sh ? sgam : gam + (size_t)ex * Ncols;
            const float* bp = sh ? sbet : bet + (size_t)ex * Ncols;
            const float* mp = sh ? smu  : mu  + (size_t)ex * Ncols;
            const float* vp = sh ? svar : var + (size_t)ex * Ncols;
            s_ep[1][tid] = gp[n0 + tid];
            s_ep[2][tid] = bp[n0 + tid];
            s_ep[3][tid] = mp[n0 + tid];
            s_ep[4][tid] = rsqrtf(vp[n0 + tid] + 1e-5f);
        }
    }

    if (wid == 0) {
        asm volatile("tcgen05.alloc.cta_group::1.sync.aligned.shared::cta.b32 [%0], %1;"
                     :: "r"(smem_u32(&s_tmem)), "r"(256) : "memory");
        asm volatile("tcgen05.relinquish_alloc_permit.cta_group::1.sync.aligned;");
    }
    if (tid == 0) {
        for (int s = 0; s < NSTAGE; ++s) mbar_init(smem_u32(&s_mbar[s]), 1);
    }
    __syncthreads();
    uint32_t tmem;
    asm volatile("ld.shared.b32 %0, [%1];" : "=r"(tmem) : "r"(smem_u32(&s_tmem)));

    // producer chunk mapping (16B chunks, SW128 swizzle on dst)
    const float* srcA[4]; uint32_t dstA[4];
#pragma unroll
    for (int i = 0; i < 4; ++i) {
        int idx = tid + i * 256;       // 0..1023
        int r = idx >> 3, c = idx & 7;
        int slot = rowBase + min(m0 + r, M - 1);
        int gr = up ? g_perm[slot] : slot;
        srcA[i] = A + (size_t)gr * Kd + c * 4;
        dstA[i] = base + (uint32_t)(r * 128 + ((c ^ (r & 7)) * 16));
    }
    const float* srcB[8]; uint32_t dstB[8];
#pragma unroll
    for (int i = 0; i < 8; ++i) {
        int idx = tid + i * 256;       // 0..2047
        int r = idx >> 3, c = idx & 7;
        srcB[i] = Bp + (size_t)(n0 + r) * Kd + c * 4;
        dstB[i] = base + A_STAGE_BYTES + (uint32_t)(r * 128 + ((c ^ (r & 7)) * 16));
    }

    int nk = Kd / BKF;

    // prologue: stages 0, 1
#pragma unroll
    for (int s = 0; s < 2; ++s) {
        uint32_t so = s * STAGE_BYTES;
        size_t  ko = (size_t)s * BKF;
#pragma unroll
        for (int i = 0; i < 4; ++i) cp16(dstA[i] + so, srcA[i] + ko);
#pragma unroll
        for (int i = 0; i < 8; ++i) cp16(dstB[i] + so, srcB[i] + ko);
        cp_commit();
    }

    // mainloop: 2-stage ring.  buffer b = kt&1; load of kt+2 requires MMA(kt) done.
    for (int kt = 0; kt < nk; ++kt) {
        cp_wait1();
        __syncthreads();

        if (tid == 0) {
            asm volatile("fence.proxy.async.shared::cta;" ::: "memory");
            uint32_t so = (uint32_t)(kt & 1) * STAGE_BYTES;
            uint64_t ad = make_desc(base + so);
            uint64_t bd = make_desc(base + so + A_STAGE_BYTES);
#pragma unroll
            for (int ks = 0; ks < 4; ++ks)
                mma5_tf32_ss(tmem, ad + ks * 2, bd + ks * 2, IDESC_TF32, (kt > 0) || (ks > 0));
            asm volatile(
                "tcgen05.commit.cta_group::1.mbarrier::arrive::one.shared::cluster.b64 [%0];"
                :: "r"(smem_u32(&s_mbar[kt & 1])) : "memory");
        }

        if (kt + 2 < nk) {
            // wait for MMA(kt) completion before overwriting its buffer
            mbar_wait(smem_u32(&s_mbar[kt & 1]), (kt >> 1) & 1);
            uint32_t so = (uint32_t)(kt & 1) * STAGE_BYTES;
            size_t  ko = (size_t)(kt + 2) * BKF;
#pragma unroll
            for (int i = 0; i < 4; ++i) cp16(dstA[i] + so, srcA[i] + ko);
#pragma unroll
            for (int i = 0; i < 8; ++i) cp16(dstB[i] + so, srcB[i] + ko);
        }
        cp_commit();
    }

    // drain: last commit covers all prior MMAs (in-order queue)
    {
        int w = nk - 1;
        mbar_wait(smem_u32(&s_mbar[w & 1]), (w >> 1) & 1);
    }
    asm volatile("tcgen05.fence::after_thread_sync;" ::: "memory");

    // epilogue: warps 0-3 read D (128 lanes x 256 cols fp32)
    if (wid < 4) {
        int mloc = wid * 32 + lane;
        int mr   = m0 + mloc;
        bool valid = (mr < M);
        float* crow = C + (size_t)(rowBase + mr) * Ncols + n0;
#pragma unroll
        for (int cc = 0; cc < 8; ++cc) {
            uint32_t r[32];
            ldtm32(r, tmem + cc * 32);
            asm volatile("tcgen05.wait::ld.sync.aligned;" ::: "memory");
            if (valid) {
#pragma unroll
                for (int j = 0; j < 32; j += 4) {
                    float o[4];
#pragma unroll
                    for (int q = 0; q < 4; ++q) {
                        int n = cc * 32 + j + q;
                        float v = __uint_as_float(r[j + q]) + s_ep[0][n];
                        if (MODE == 0) {
                            v = fmaxf(v, 0.f);
                            v = s_ep[1][n] * (v - s_ep[3][n]) * s_ep[4][n] + s_ep[2][n];
                        } else {
                            v = 1.f / (1.f + expf(-v));
                        }
                        o[q] = v;
                    }
                    *(float4*)(crow + cc * 32 + j) = make_float4(o[0], o[1], o[2], o[3]);
                }
            }
        }
    }

    __syncthreads();
    if (wid == 0) {
        asm volatile("tcgen05.dealloc.cta_group::1.sync.aligned.b32 %0, %1;"
                     :: "r"(tmem), "r"(256));
    }

#else
    // ================= mma.sync tf32 fallback engine =================
    float* AsBase = dyn;
    float* BsBase = dyn + FB_STAGES * BM * SP;

    int wm   = wid & 1;
    int wn   = wid >> 1;
    int g    = lane >> 2;
    int t    = lane & 3;

    int rA[2], kA[2];
    const float* srcA[2];
    uint32_t dA[2];
    uint32_t sA = smem_u32(AsBase);
    uint32_t sB = smem_u32(BsBase);
#pragma unroll
    for (int i = 0; i < 2; ++i) {
        int c = tid + i * 256;
        rA[i] = c >> 2; kA[i] = (c & 3) * 4;
        int slot = rowBase + min(m0 + rA[i], M - 1);
        int gr = up ? g_perm[slot] : slot;
        srcA[i] = A + (size_t)gr * Kd + kA[i];
        dA[i] = sA + (uint32_t)(rA[i] * SP + kA[i]) * 4;
    }
    const float* srcB[4];
    uint32_t dB[4];
#pragma unroll
    for (int i = 0; i < 4; ++i) {
        int c = tid + i * 256;
        int rB = c >> 2, kB = (c & 3) * 4;
        srcB[i] = Bp + (size_t)(n0 + rB) * Kd + kB;
        dB[i] = sB + (uint32_t)(rB * SP + kB) * 4;
    }
    const uint32_t stA = BM * SP * 4;
    const uint32_t stB = BN * SP * 4;

    float acc[4][8][4];
#pragma unroll
    for (int i = 0; i < 4; ++i)
#pragma unroll
        for (int j = 0; j < 8; ++j)
#pragma unroll
            for (int q = 0; q < 4; ++q) acc[i][j][q] = 0.f;

    int nk = Kd >> 4;

#pragma unroll
    for (int s = 0; s < 2; ++s) {
        size_t ko = (size_t)s * FB_BK;
#pragma unroll
        for (int i = 0; i < 2; ++i) cp16(dA[i] + s * stA, srcA[i] + ko);
#pragma unroll
        for (int i = 0; i < 4; ++i) cp16(dB[i] + s * stB, srcB[i] + ko);
        cp_commit();
    }

    for (int kt = 0; kt < nk; ++kt) {
        cp_wait1();
        __syncthreads();

        if (kt + 2 < nk) {
            int s = (kt + 2) % FB_STAGES;
            size_t ko = (size_t)(kt + 2) * FB_BK;
#pragma unroll
            for (int i = 0; i < 2; ++i) cp16(dA[i] + s * stA, srcA[i] + ko);
#pragma unroll
            for (int i = 0; i < 4; ++i) cp16(dB[i] + s * stB, srcB[i] + ko);
        }
        cp_commit();

        int cur = kt % FB_STAGES;
        const float* As = AsBase + cur * BM * SP;
        const float* Bs = BsBase + cur * BN * SP;

#pragma unroll
        for (int kk = 0; kk < FB_BK; kk += 8) {
            uint32_t a[4][4], b[8][2];
#pragma unroll
            for (int mi = 0; mi < 4; ++mi) {
                int r = wm * 64 + mi * 16 + g;
                a[mi][0] = __float_as_uint(As[(r    ) * SP + kk + t]);
                a[mi][1] = __float_as_uint(As[(r + 8) * SP + kk + t]);
                a[mi][2] = __float_as_uint(As[(r    ) * SP + kk + t + 4]);
                a[mi][3] = __float_as_uint(As[(r + 8) * SP + kk + t + 4]);
            }
#pragma unroll
            for (int ni = 0; ni < 8; ++ni) {
                int r = wn * 64 + ni * 8 + g;
                b[ni][0] = __float_as_uint(Bs[r * SP + kk + t]);
                b[ni][1] = __float_as_uint(Bs[r * SP + kk + t + 4]);
            }
#pragma unroll
            for (int mi = 0; mi < 4; ++mi)
#pragma unroll
                for (int ni = 0; ni < 8; ++ni)
                    mma_tf32(acc[mi][ni], a[mi], b[ni]);
        }
    }

    const float* gp = (MODE == 0) ? (sh ? sgam : gam + (size_t)ex * Ncols) : nullptr;
    const float* bp = (MODE == 0) ? (sh ? sbet : bet + (size_t)ex * Ncols) : nullptr;
    const float* mp = (MODE == 0) ? (sh ? smu  : mu  + (size_t)ex * Ncols) : nullptr;
    const float* vp = (MODE == 0) ? (sh ? svar : var + (size_t)ex * Ncols) : nullptr;

#pragma unroll
    for (int ni = 0; ni < 8; ++ni) {
        int cb = n0 + wn * 64 + ni * 8 + 2 * t;
        float bb0 = biasp[cb], bb1 = biasp[cb + 1];
        float gg0 = 0, gg1 = 0, be0 = 0, be1 = 0, mm0 = 0, mm1 = 0, iv0 = 0, iv1 = 0;
        if (MODE == 0) {
            gg0 = gp[cb]; gg1 = gp[cb + 1];
            be0 = bp[cb]; be1 = bp[cb + 1];
            mm0 = mp[cb]; mm1 = mp[cb + 1];
            iv0 = rsqrtf(vp[cb] + 1e-5f);
            iv1 = rsqrtf(vp[cb + 1] + 1e-5f);
        }
#pragma unroll
        for (int mi = 0; mi < 4; ++mi) {
#pragma unroll
            for (int half = 0; half < 2; ++half) {
                int mr = m0 + wm * 64 + mi * 16 + g + half * 8;
                if (mr < M) {
                    float v0 = acc[mi][ni][half * 2 + 0] + bb0;
                    float v1 = acc[mi][ni][half * 2 + 1] + bb1;
                    if (MODE == 0) {
                        v0 = fmaxf(v0, 0.f);
                        v1 = fmaxf(v1, 0.f);
                        v0 = gg0 * (v0 - mm0) * iv0 + be0;
                        v1 = gg1 * (v1 - mm1) * iv1 + be1;
                    } else {
                        v0 = 1.f / (1.f + expf(-v0));
                        v1 = 1.f / (1.f + expf(-v1));
                    }
                    float* crow = C + (size_t)(rowBase + mr) * Ncols + cb;
                    *(float2*)crow = make_float2(v0, v1);
                }
            }
        }
    }
#endif  // TC5
}

// ---------------- combine ----------------
__global__ void combine_kernel(float* __restrict__ out) {
    int n = blockIdx.x;
    int e0 = g_eid[2 * n + 0], e1 = g_eid[2 * n + 1];
    int s0 = g_offs[e0] + g_pos[2 * n + 0];
    int s1 = g_offs[e1] + g_pos[2 * n + 1];
    float w0 = g_w[2 * n + 0], w1 = g_w[2 * n + 1];
    const float* r0 = g_eo + (size_t)s0 * OUTD;
    const float* r1 = g_eo + (size_t)s1 * OUTD;
    float* orow = out + (size_t)n * OUTD;
    for (int c = threadIdx.x; c < OUTD; c += blockDim.x)
        orow[c] += w0 * r0[c] + w1 * r1[c];
}

// ---------------- launch ----------------
extern "C" void kernel_launch(void* const* d_in, const int* in_sizes, int n_in,
                              void* d_out, int out_size) {
    const float* x   = (const float*)d_in[0];
    const float* Wg  = (const float*)d_in[1];
    const float* W1  = (const float*)d_in[2];
    const float* b1  = (const float*)d_in[3];
    const float* g1  = (const float*)d_in[4];
    const float* be1 = (const float*)d_in[5];
    const float* m1  = (const float*)d_in[6];
    const float* v1  = (const float*)d_in[7];
    const float* W2  = (const float*)d_in[8];
    const float* b2  = (const float*)d_in[9];
    const float* g2  = (const float*)d_in[10];
    const float* be2 = (const float*)d_in[11];
    const float* m2  = (const float*)d_in[12];
    const float* v2  = (const float*)d_in[13];
    const float* W3  = (const float*)d_in[14];
    const float* b3  = (const float*)d_in[15];
    const float* sW1 = (const float*)d_in[16];
    const float* sb1 = (const float*)d_in[17];
    const float* sg1 = (const float*)d_in[18];
    const float* sbe1= (const float*)d_in[19];
    const float* sm1 = (const float*)d_in[20];
    const float* sv1 = (const float*)d_in[21];
    const float* sW2 = (const float*)d_in[22];
    const float* sb2 = (const float*)d_in[23];
    const float* sg2 = (const float*)d_in[24];
    const float* sbe2= (const float*)d_in[25];
    const float* sm2 = (const float*)d_in[26];
    const float* sv2 = (const float*)d_in[27];
    const float* sW3 = (const float*)d_in[28];
    const float* sb3 = (const float*)d_in[29];
    float* out = (float*)d_out;

    cudaFuncSetAttribute(gemm5<0>, cudaFuncAttributeMaxDynamicSharedMemorySize, DYN_SMEM);
    cudaFuncSetAttribute(gemm5<1>, cudaFuncAttributeMaxDynamicSharedMemorySize, DYN_SMEM);

    reset_kernel<<<1, 32>>>();
    gate_kernel<<<NTOK / 8, 256>>>(x, Wg);
    scan_kernel<<<1, 1>>>();
    compact_kernel<<<NEXP, 256>>>();

    // layer 1: x -> h1 (routed, perm-gather) and x -> s1 (shared)
    gemm5<0><<<dim3((NEXP + 1) * (HID / BN), NTOK / BM, 1), 256, DYN_SMEM>>>(
        0, 1, 0, 3, x, out, W1, sW1, b1, sb1, g1, sg1, be1, sbe1, m1, sm1, v1, sv1,
        1, DIM, HID, HID / BN);
    // layer 2: h1 -> h2 (routed) and s1 -> s2 (shared)
    gemm5<0><<<dim3((NEXP + 1) * (HID / BN), NTOK / BM, 1), 256, DYN_SMEM>>>(
        1, 2, 3, 4, x, out, W2, sW2, b2, sb2, g2, sg2, be2, sbe2, m2, sm2, v2, sv2,
        0, HID, HID, HID / BN);
    // layer 3: h2 -> eo (routed, sigmoid) and s2 -> out (shared, sigmoid)
    gemm5<1><<<dim3((NEXP + 1) * (OUTD / BN), NTOK / BM, 1), 256, DYN_SMEM>>>(
        2, 5, 4, 6, x, out, W3, sW3, b3, sb3,
        nullptr, nullptr, nullptr, nullptr, nullptr, nullptr, nullptr, nullptr,
        0, HID, OUTD, OUTD / BN);

    combine_kernel<<<NTOK, 256>>>(out);
}

// round 11
// speedup vs baseline: 1.2721x; 1.1476x over previous
#include <cuda_runtime.h>
#include <cuda_fp16.h>
#include <math.h>
#include <stdint.h>

// ---------------- problem constants ----------------
#define NTOK 8192
#define DIM  1024
#define HID  2048
#define OUTD 1024
#define NEXP 8
#define TOPK 2

// ---------------- tiling ----------------
#define BM 128
#define BN 256
#define BKF 64                        // K halves per stage (= 128 B rows)
#define NSTAGE 2
#define A_STAGE_BYTES (BM * 128)      // 16 KB
#define B_STAGE_BYTES (BN * 128)      // 32 KB
#define STAGE_BYTES (A_STAGE_BYTES + B_STAGE_BYTES)   // 48 KB
#define DYN_SMEM (NSTAGE * STAGE_BYTES + 1024)        // 99328
// idesc kind::f16, fp16 inputs: dtype=F32(1@4), atype=F16(0), btype=F16(0), N/8@17, M/16@24
#define IDESC_F16 ((1u << 4) | ((BN / 8) << 17) | ((BM / 16) << 24))

#if defined(__CUDA_ARCH_FEAT_SM103_ALL) || defined(__CUDA_ARCH_FEAT_SM100_ALL) || \
    defined(__CUDA_ARCH_FEAT_SM101_ALL) || defined(__CUDA_ARCH_FEAT_SM110_ALL)
#define TC5 1
#else
#define TC5 0
#endif

// ---------------- device scratch ----------------
// fp16 operand buffers
__device__ __half g_xh[(size_t)NTOK * DIM];
__device__ __half g_w1h[(size_t)NEXP * HID * DIM];
__device__ __half g_w2h[(size_t)NEXP * HID * HID];
__device__ __half g_w3h[(size_t)NEXP * OUTD * HID];
__device__ __half g_sw1h[(size_t)HID * DIM];
__device__ __half g_sw2h[(size_t)HID * HID];
__device__ __half g_sw3h[(size_t)OUTD * HID];
__device__ __half g_h1h[(size_t)TOPK * NTOK * HID];
__device__ __half g_h2h[(size_t)TOPK * NTOK * HID];
__device__ __half g_s1h[(size_t)NTOK * HID];
__device__ __half g_s2h[(size_t)NTOK * HID];
// fp32 outputs of layer 3
__device__ float g_eo[(size_t)TOPK * NTOK * OUTD];
// routing
__device__ int   g_cnt[NEXP];
__device__ int   g_offs[NEXP + 1];
__device__ int   g_tmp[NEXP * NTOK];
__device__ int   g_perm[TOPK * NTOK];
__device__ int   g_eid[TOPK * NTOK];
__device__ int   g_pos[TOPK * NTOK];
__device__ float g_w[TOPK * NTOK];

__device__ __forceinline__ const __half* abuf_ptr(int sel) {
    switch (sel) {
        case 0: return g_xh;
        case 1: return g_h1h;
        case 2: return g_h2h;
        case 3: return g_s1h;
        default: return g_s2h;
    }
}
__device__ __forceinline__ __half* hbuf_ptr(int sel) {
    switch (sel) {
        case 1: return g_h1h;
        case 2: return g_h2h;
        case 3: return g_s1h;
        default: return g_s2h;
    }
}

// ---------------- common helpers ----------------
__device__ __forceinline__ uint32_t smem_u32(const void* p) {
    return (uint32_t)__cvta_generic_to_shared(p);
}
__device__ __forceinline__ void cp16(uint32_t dst, const void* src) {
    asm volatile("cp.async.cg.shared.global [%0], [%1], 16;\n" :: "r"(dst), "l"(src));
}
__device__ __forceinline__ void cp_commit() {
    asm volatile("cp.async.commit_group;\n" ::);
}
__device__ __forceinline__ void cp_wait1() {
    asm volatile("cp.async.wait_group 1;\n" ::);
}

#if TC5
__device__ __forceinline__ void mbar_init(uint32_t addr, uint32_t cnt) {
    asm volatile("mbarrier.init.shared.b64 [%0], %1;" :: "r"(addr), "r"(cnt) : "memory");
}
__device__ __forceinline__ void mbar_wait(uint32_t addr, uint32_t parity) {
    asm volatile(
        "{\n\t"
        ".reg .pred P1;\n\t"
        "WAIT_LOOP_%=:\n\t"
        "mbarrier.try_wait.parity.acquire.cta.shared::cta.b64 P1, [%0], %1, 0x989680;\n\t"
        "@P1 bra.uni WAIT_DONE_%=;\n\t"
        "bra.uni WAIT_LOOP_%=;\n\t"
        "WAIT_DONE_%=:\n\t"
        "}"
        :: "r"(addr), "r"(parity) : "memory");
}
// SW128 K-major descriptor: layout=2, version=1, SBO=64, LBO=1
__device__ __forceinline__ uint64_t make_desc(uint32_t addr) {
    return (uint64_t(2) << 61) | (uint64_t(1) << 46) | (uint64_t(64) << 32)
         | (uint64_t(1) << 16) | ((uint64_t)(addr >> 4) & 0x3FFF);
}
__device__ __forceinline__ void mma5_f16_ss(uint32_t d_tmem, uint64_t a_desc, uint64_t b_desc,
                                            uint32_t idesc, bool acc) {
    uint32_t en = acc ? 1u : 0u;
    asm volatile(
        "{\n\t"
        ".reg .pred p;\n\t"
        "setp.ne.u32 p, %5, 0;\n\t"
        "tcgen05.mma.cta_group::1.kind::f16 [%0], %1, %2, %3, {%4, %4, %4, %4}, p;\n\t"
        "}"
        :: "r"(d_tmem), "l"(a_desc), "l"(b_desc), "r"(idesc), "r"(0u), "r"(en)
        : "memory");
}
__device__ __forceinline__ void ldtm32(uint32_t* r, uint32_t tmem_addr) {
    asm volatile(
        "tcgen05.ld.sync.aligned.32x32b.x32.b32 "
        "{%0, %1, %2, %3, %4, %5, %6, %7, "
        " %8, %9, %10, %11, %12, %13, %14, %15, "
        " %16, %17, %18, %19, %20, %21, %22, %23, "
        " %24, %25, %26, %27, %28, %29, %30, %31}, [%32];"
        : "=r"(r[0]),  "=r"(r[1]),  "=r"(r[2]),  "=r"(r[3]),
          "=r"(r[4]),  "=r"(r[5]),  "=r"(r[6]),  "=r"(r[7]),
          "=r"(r[8]),  "=r"(r[9]),  "=r"(r[10]), "=r"(r[11]),
          "=r"(r[12]), "=r"(r[13]), "=r"(r[14]), "=r"(r[15]),
          "=r"(r[16]), "=r"(r[17]), "=r"(r[18]), "=r"(r[19]),
          "=r"(r[20]), "=r"(r[21]), "=r"(r[22]), "=r"(r[23]),
          "=r"(r[24]), "=r"(r[25]), "=r"(r[26]), "=r"(r[27]),
          "=r"(r[28]), "=r"(r[29]), "=r"(r[30]), "=r"(r[31])
        : "r"(tmem_addr));
}
#endif  // TC5

// ---------------- fp32 -> fp16 convert ----------------
__global__ void f2h_kernel(const float* __restrict__ in, __half* __restrict__ out, int n) {
    int stride = gridDim.x * blockDim.x * 4;
    for (int i = (blockIdx.x * blockDim.x + threadIdx.x) * 4; i < n; i += stride) {
        float4 v = *(const float4*)(in + i);
        __half2 a = __floats2half2_rn(v.x, v.y);
        __half2 b = __floats2half2_rn(v.z, v.w);
        *(__half2*)(out + i)     = a;
        *(__half2*)(out + i + 2) = b;
    }
}

// ---------------- reset / gate / scan / compact ----------------
__global__ void reset_kernel() {
    if (threadIdx.x < NEXP) g_cnt[threadIdx.x] = 0;
}

__global__ void gate_kernel(const float* __restrict__ x, const float* __restrict__ Wg) {
    int gwarp = (blockIdx.x * blockDim.x + threadIdx.x) >> 5;
    int lane  = threadIdx.x & 31;
    if (gwarp >= NTOK) return;
    const float* xr = x + (size_t)gwarp * DIM;

    float sc[NEXP];
#pragma unroll
    for (int e = 0; e < NEXP; ++e) {
        const float* wr = Wg + (size_t)e * DIM;
        float s = 0.f;
        for (int d = lane; d < DIM; d += 32) s += xr[d] * wr[d];
#pragma unroll
        for (int o = 16; o > 0; o >>= 1) s += __shfl_xor_sync(0xffffffffu, s, o);
        sc[e] = s;
    }
    if (lane == 0) {
        float mx = sc[0];
#pragma unroll
        for (int e = 1; e < NEXP; ++e) mx = fmaxf(mx, sc[e]);
        float ex[NEXP], sum = 0.f;
#pragma unroll
        for (int e = 0; e < NEXP; ++e) { ex[e] = expf(sc[e] - mx); sum += ex[e]; }
        float p[NEXP];
#pragma unroll
        for (int e = 0; e < NEXP; ++e) p[e] = ex[e] / sum;
        int i0 = 0;
#pragma unroll
        for (int e = 1; e < NEXP; ++e) if (p[e] > p[i0]) i0 = e;
        int i1 = -1;
#pragma unroll
        for (int e = 0; e < NEXP; ++e) {
            if (e == i0) continue;
            if (i1 < 0 || p[e] > p[i1]) i1 = e;
        }
        float p0 = p[i0], p1 = p[i1];
        float s2 = p0 + p1 + 1e-20f;
        float w0 = p0 / s2, w1 = p1 / s2;

        int pos0 = atomicAdd(&g_cnt[i0], 1);
        g_tmp[i0 * NTOK + pos0] = gwarp;
        int pos1 = atomicAdd(&g_cnt[i1], 1);
        g_tmp[i1 * NTOK + pos1] = gwarp;

        g_eid[2 * gwarp + 0] = i0; g_pos[2 * gwarp + 0] = pos0; g_w[2 * gwarp + 0] = w0;
        g_eid[2 * gwarp + 1] = i1; g_pos[2 * gwarp + 1] = pos1; g_w[2 * gwarp + 1] = w1;
    }
}

__global__ void scan_kernel() {
    if (threadIdx.x == 0) {
        int acc = 0;
        g_offs[0] = 0;
        for (int e = 0; e < NEXP; ++e) { acc += g_cnt[e]; g_offs[e + 1] = acc; }
    }
}

__global__ void compact_kernel() {
    int e = blockIdx.x;
    int base = g_offs[e];
    int c = g_cnt[e];
    for (int i = threadIdx.x; i < c; i += blockDim.x)
        g_perm[base + i] = g_tmp[e * NTOK + i];
}

// ---------------- merged fp16 tcgen05 NT GEMM ----------------
// blockIdx.x = ex * xTiles + xt; ex in [0, NEXP] where NEXP == shared expert.
// C[m,n] = epi( sum_k A[m,k]*B[n,k] + bias[n] ).
// MODE 0: relu->BN, write fp16.  MODE 1: sigmoid, write fp32 (g_eo / out).
template<int MODE>
__global__ void __launch_bounds__(256, 2) __cluster_dims__(1, 1, 1)
gemm5(int aSelR, int cSelR, int aSelS, int cSelS,
      float* __restrict__ outp,
      const __half* __restrict__ W,   const __half* __restrict__ sW,
      const float* __restrict__ bias, const float* __restrict__ sbias,
      const float* __restrict__ gam,  const float* __restrict__ sgam,
      const float* __restrict__ bet,  const float* __restrict__ sbet,
      const float* __restrict__ mu,   const float* __restrict__ smu,
      const float* __restrict__ var,  const float* __restrict__ svar,
      int usePerm, int Kd, int Ncols, int xTiles)
{
    extern __shared__ float dyn[];

    int ex = blockIdx.x / xTiles;
    int xt = blockIdx.x - ex * xTiles;
    bool sh = (ex == NEXP);

    int M       = sh ? NTOK : g_cnt[ex];
    int rowBase = sh ? 0    : g_offs[ex];
    int m0 = blockIdx.y * BM;
    if (m0 >= M) return;
    int n0 = xt * BN;

    const __half* A  = abuf_ptr(sh ? aSelS : aSelR);
    const __half* Bp = sh ? sW    : W    + (size_t)ex * Ncols * Kd;
    const float* biasp = sh ? sbias : bias + (size_t)ex * Ncols;
    int up = sh ? 0 : usePerm;

    int tid = threadIdx.x, wid = tid >> 5, lane = tid & 31;

#if TC5
    __shared__ uint64_t s_mbar[NSTAGE];
    __shared__ uint32_t s_tmem;
    __shared__ float    s_ep[5][BN];

    uint32_t base = (smem_u32(dyn) + 1023u) & ~1023u;

    {   // epilogue params -> smem (one column per thread)
        s_ep[0][tid] = biasp[n0 + tid];
        if (MODE == 0) {
            const float* gp = sh ? sgam : gam + (size_t)ex * Ncols;
            const float* bp = sh ? sbet : bet + (size_t)ex * Ncols;
            const float* mp = sh ? smu  : mu  + (size_t)ex * Ncols;
            const float* vp = sh ? svar : var + (size_t)ex * Ncols;
            s_ep[1][tid] = gp[n0 + tid];
            s_ep[2][tid] = bp[n0 + tid];
            s_ep[3][tid] = mp[n0 + tid];
            s_ep[4][tid] = rsqrtf(vp[n0 + tid] + 1e-5f);
        }
    }

    if (wid == 0) {
        asm volatile("tcgen05.alloc.cta_group::1.sync.aligned.shared::cta.b32 [%0], %1;"
                     :: "r"(smem_u32(&s_tmem)), "r"(256) : "memory");
        asm volatile("tcgen05.relinquish_alloc_permit.cta_group::1.sync.aligned;");
    }
    if (tid == 0) {
        for (int s = 0; s < NSTAGE; ++s) mbar_init(smem_u32(&s_mbar[s]), 1);
    }
    __syncthreads();
    uint32_t tmem;
    asm volatile("ld.shared.b32 %0, [%1];" : "=r"(tmem) : "r"(smem_u32(&s_tmem)));

    // producer chunk mapping (16B = 8 halves per chunk, SW128 swizzle on dst)
    const __half* srcA[4]; uint32_t dstA[4];
#pragma unroll
    for (int i = 0; i < 4; ++i) {
        int idx = tid + i * 256;       // 0..1023
        int r = idx >> 3, c = idx & 7;
        int slot = rowBase + min(m0 + r, M - 1);
        int gr = up ? g_perm[slot] : slot;
        srcA[i] = A + (size_t)gr * Kd + c * 8;
        dstA[i] = base + (uint32_t)(r * 128 + ((c ^ (r & 7)) * 16));
    }
    const __half* srcB[8]; uint32_t dstB[8];
#pragma unroll
    for (int i = 0; i < 8; ++i) {
        int idx = tid + i * 256;       // 0..2047
        int r = idx >> 3, c = idx & 7;
        srcB[i] = Bp + (size_t)(n0 + r) * Kd + c * 8;
        dstB[i] = base + A_STAGE_BYTES + (uint32_t)(r * 128 + ((c ^ (r & 7)) * 16));
    }

    int nk = Kd / BKF;

    // prologue: stages 0, 1
#pragma unroll
    for (int s = 0; s < 2; ++s) {
        uint32_t so = s * STAGE_BYTES;
        size_t  ko = (size_t)s * BKF;
#pragma unroll
        for (int i = 0; i < 4; ++i) cp16(dstA[i] + so, srcA[i] + ko);
#pragma unroll
        for (int i = 0; i < 8; ++i) cp16(dstB[i] + so, srcB[i] + ko);
        cp_commit();
    }

    // mainloop: 2-stage ring
    for (int kt = 0; kt < nk; ++kt) {
        cp_wait1();
        __syncthreads();

        if (tid == 0) {
            asm volatile("fence.proxy.async.shared::cta;" ::: "memory");
            uint32_t so = (uint32_t)(kt & 1) * STAGE_BYTES;
            uint64_t ad = make_desc(base + so);
            uint64_t bd = make_desc(base + so + A_STAGE_BYTES);
#pragma unroll
            for (int ks = 0; ks < 4; ++ks)   // 4 x K=16 per stage
                mma5_f16_ss(tmem, ad + ks * 2, bd + ks * 2, IDESC_F16, (kt > 0) || (ks > 0));
            asm volatile(
                "tcgen05.commit.cta_group::1.mbarrier::arrive::one.shared::cluster.b64 [%0];"
                :: "r"(smem_u32(&s_mbar[kt & 1])) : "memory");
        }

        if (kt + 2 < nk) {
            mbar_wait(smem_u32(&s_mbar[kt & 1]), (kt >> 1) & 1);
            uint32_t so = (uint32_t)(kt & 1) * STAGE_BYTES;
            size_t  ko = (size_t)(kt + 2) * BKF;
#pragma unroll
            for (int i = 0; i < 4; ++i) cp16(dstA[i] + so, srcA[i] + ko);
#pragma unroll
            for (int i = 0; i < 8; ++i) cp16(dstB[i] + so, srcB[i] + ko);
        }
        cp_commit();
    }

    {
        int w = nk - 1;
        mbar_wait(smem_u32(&s_mbar[w & 1]), (w >> 1) & 1);
    }
    asm volatile("tcgen05.fence::after_thread_sync;" ::: "memory");

    // epilogue: warps 0-3 read D (128 lanes x 256 cols fp32)
    if (wid < 4) {
        int mloc = wid * 32 + lane;
        int mr   = m0 + mloc;
        bool valid = (mr < M);
        float* crowF = nullptr;
        __half* crowH = nullptr;
        if (MODE == 1) {
            float* C = (cSelR == 6 || (sh && cSelS == 6)) ? outp : g_eo;
            C = sh ? ((cSelS == 6) ? outp : g_eo) : ((cSelR == 6) ? outp : g_eo);
            crowF = C + (size_t)(rowBase + mr) * Ncols + n0;
        } else {
            __half* C = hbuf_ptr(sh ? cSelS : cSelR);
            crowH = C + (size_t)(rowBase + mr) * Ncols + n0;
        }
#pragma unroll
        for (int cc = 0; cc < 8; ++cc) {
            uint32_t r[32];
            ldtm32(r, tmem + cc * 32);
            asm volatile("tcgen05.wait::ld.sync.aligned;" ::: "memory");
            if (valid) {
#pragma unroll
                for (int j = 0; j < 32; j += 4) {
                    float o[4];
#pragma unroll
                    for (int q = 0; q < 4; ++q) {
                        int n = cc * 32 + j + q;
                        float v = __uint_as_float(r[j + q]) + s_ep[0][n];
                        if (MODE == 0) {
                            v = fmaxf(v, 0.f);
                            v = s_ep[1][n] * (v - s_ep[3][n]) * s_ep[4][n] + s_ep[2][n];
                        } else {
                            v = 1.f / (1.f + expf(-v));
                        }
                        o[q] = v;
                    }
                    if (MODE == 0) {
                        __half2 p0 = __floats2half2_rn(o[0], o[1]);
                        __half2 p1 = __floats2half2_rn(o[2], o[3]);
                        __half2* dst = (__half2*)(crowH + cc * 32 + j);
                        dst[0] = p0; dst[1] = p1;
                    } else {
                        *(float4*)(crowF + cc * 32 + j) = make_float4(o[0], o[1], o[2], o[3]);
                    }
                }
            }
        }
    }

    __syncthreads();
    if (wid == 0) {
        asm volatile("tcgen05.dealloc.cta_group::1.sync.aligned.b32 %0, %1;"
                     :: "r"(tmem), "r"(256));
    }

#else
    // ---------- naive correct fallback (never used on GB300 bench) ----------
    (void)dyn;
    for (int idx = tid; idx < BM * BN; idx += 256) {
        int mi = idx / BN, ni = idx - mi * BN;
        int mr = m0 + mi;
        if (mr >= M) continue;
        int slot = rowBase + mr;
        int gr = up ? g_perm[slot] : slot;
        const __half* ar = A + (size_t)gr * Kd;
        const __half* br = Bp + (size_t)(n0 + ni) * Kd;
        float acc = 0.f;
        for (int k = 0; k < Kd; ++k)
            acc += __half2float(ar[k]) * __half2float(br[k]);
        int n = n0 + ni;
        float v = acc + biasp[n];
        if (MODE == 0) {
            const float* gp = sh ? sgam : gam + (size_t)ex * Ncols;
            const float* bp = sh ? sbet : bet + (size_t)ex * Ncols;
            const float* mp = sh ? smu  : mu  + (size_t)ex * Ncols;
            const float* vp = sh ? svar : var + (size_t)ex * Ncols;
            v = fmaxf(v, 0.f);
            v = gp[n] * (v - mp[n]) * rsqrtf(vp[n] + 1e-5f) + bp[n];
            __half* C = hbuf_ptr(sh ? cSelS : cSelR);
            C[(size_t)slot * Ncols + n] = __float2half_rn(v);
        } else {
            v = 1.f / (1.f + expf(-v));
            float* C = sh ? ((cSelS == 6) ? outp : g_eo) : ((cSelR == 6) ? outp : g_eo);
            C[(size_t)slot * Ncols + n] = v;
        }
    }
#endif  // TC5
}

// ---------------- combine ----------------
__global__ void combine_kernel(float* __restrict__ out) {
    int n = blockIdx.x;
    int e0 = g_eid[2 * n + 0], e1 = g_eid[2 * n + 1];
    int s0 = g_offs[e0] + g_pos[2 * n + 0];
    int s1 = g_offs[e1] + g_pos[2 * n + 1];
    float w0 = g_w[2 * n + 0], w1 = g_w[2 * n + 1];
    const float* r0 = g_eo + (size_t)s0 * OUTD;
    const float* r1 = g_eo + (size_t)s1 * OUTD;
    float* orow = out + (size_t)n * OUTD;
    for (int c = threadIdx.x; c < OUTD; c += blockDim.x)
        orow[c] += w0 * r0[c] + w1 * r1[c];
}

// ---------------- launch ----------------
extern "C" void kernel_launch(void* const* d_in, const int* in_sizes, int n_in,
                              void* d_out, int out_size) {
    const float* x   = (const float*)d_in[0];
    const float* Wg  = (const float*)d_in[1];
    const float* W1  = (const float*)d_in[2];
    const float* b1  = (const float*)d_in[3];
    const float* g1  = (const float*)d_in[4];
    const float* be1 = (const float*)d_in[5];
    const float* m1  = (const float*)d_in[6];
    const float* v1  = (const float*)d_in[7];
    const float* W2  = (const float*)d_in[8];
    const float* b2  = (const float*)d_in[9];
    const float* g2  = (const float*)d_in[10];
    const float* be2 = (const float*)d_in[11];
    const float* m2  = (const float*)d_in[12];
    const float* v2  = (const float*)d_in[13];
    const float* W3  = (const float*)d_in[14];
    const float* b3  = (const float*)d_in[15];
    const float* sW1 = (const float*)d_in[16];
    const float* sb1 = (const float*)d_in[17];
    const float* sg1 = (const float*)d_in[18];
    const float* sbe1= (const float*)d_in[19];
    const float* sm1 = (const float*)d_in[20];
    const float* sv1 = (const float*)d_in[21];
    const float* sW2 = (const float*)d_in[22];
    const float* sb2 = (const float*)d_in[23];
    const float* sg2 = (const float*)d_in[24];
    const float* sbe2= (const float*)d_in[25];
    const float* sm2 = (const float*)d_in[26];
    const float* sv2 = (const float*)d_in[27];
    const float* sW3 = (const float*)d_in[28];
    const float* sb3 = (const float*)d_in[29];
    float* out = (float*)d_out;

    cudaFuncSetAttribute(gemm5<0>, cudaFuncAttributeMaxDynamicSharedMemorySize, DYN_SMEM);
    cudaFuncSetAttribute(gemm5<1>, cudaFuncAttributeMaxDynamicSharedMemorySize, DYN_SMEM);

    reset_kernel<<<1, 32>>>();
    gate_kernel<<<NTOK / 8, 256>>>(x, Wg);
    scan_kernel<<<1, 1>>>();
    compact_kernel<<<NEXP, 256>>>();

    // fp32 -> fp16 operand conversion (deterministic, every call)
    __half *xh, *w1h, *w2h, *w3h, *sw1h, *sw2h, *sw3h;
    cudaGetSymbolAddress((void**)&xh,  g_xh);
    cudaGetSymbolAddress((void**)&w1h, g_w1h);
    cudaGetSymbolAddress((void**)&w2h, g_w2h);
    cudaGetSymbolAddress((void**)&w3h, g_w3h);
    cudaGetSymbolAddress((void**)&sw1h, g_sw1h);
    cudaGetSymbolAddress((void**)&sw2h, g_sw2h);
    cudaGetSymbolAddress((void**)&sw3h, g_sw3h);
    f2h_kernel<<<2048, 256>>>(x,   xh,  NTOK * DIM);
    f2h_kernel<<<4096, 256>>>(W1,  w1h, NEXP * HID * DIM);
    f2h_kernel<<<8192, 256>>>(W2,  w2h, NEXP * HID * HID);
    f2h_kernel<<<4096, 256>>>(W3,  w3h, NEXP * OUTD * HID);
    f2h_kernel<<<1024, 256>>>(sW1, sw1h, HID * DIM);
    f2h_kernel<<<2048, 256>>>(sW2, sw2h, HID * HID);
    f2h_kernel<<<1024, 256>>>(sW3, sw3h, OUTD * HID);

    // layer 1: x -> h1 (routed, perm-gather) and x -> s1 (shared)
    gemm5<0><<<dim3((NEXP + 1) * (HID / BN), NTOK / BM, 1), 256, DYN_SMEM>>>(
        0, 1, 0, 3, out, w1h, sw1h, b1, sb1, g1, sg1, be1, sbe1, m1, sm1, v1, sv1,
        1, DIM, HID, HID / BN);
    // layer 2: h1 -> h2 (routed) and s1 -> s2 (shared)
    gemm5<0><<<dim3((NEXP + 1) * (HID / BN), NTOK / BM, 1), 256, DYN_SMEM>>>(
        1, 2, 3, 4, out, w2h, sw2h, b2, sb2, g2, sg2, be2, sbe2, m2, sm2, v2, sv2,
        0, HID, HID, HID / BN);
    // layer 3: h2 -> eo (routed, sigmoid, fp32) and s2 -> out (shared, sigmoid, fp32)
    gemm5<1><<<dim3((NEXP + 1) * (OUTD / BN), NTOK / BM, 1), 256, DYN_SMEM>>>(
        2, 5, 4, 6, out, w3h, sw3h, b3, sb3,
        nullptr, nullptr, nullptr, nullptr, nullptr, nullptr, nullptr, nullptr,
        0, HID, OUTD, OUTD / BN);

    combine_kernel<<<NTOK, 256>>>(out);
}